// round 11
// baseline (speedup 1.0000x reference)
#include <cuda_runtime.h>
#include <cuda_bf16.h>
#include <cstdint>

#define Bb 4
#define Nn 4096
#define KK 16
#define DP 64
#define DM 128
#define BN (Bb*Nn)

// ---- scratch (device globals: allocation-free) ----
__device__ int   g_knn[BN*KK];
__device__ float g_Q [BN*DM];
__device__ float g_Kf[BN*DM];
__device__ float g_Vf[BN*DM];
// pre-split/transposed/swizzled weight tile images:
// [gemm(3)][half hi/lo][ktile(2)] x (128 rows x 64 bf16) = 12 x 16KB
__device__ __nv_bfloat16 g_Wb[3*2*2*128*64];

#define KV_STR 136   // floats per staged K/V row (bank spreading, 16B aligned)

// ============================================================
// helpers
// ============================================================
__device__ __forceinline__ uint32_t s2u(const void* p) {
    uint32_t a;
    asm("{ .reg .u64 t; cvta.to.shared.u64 t, %1; cvt.u32.u64 %0, t; }"
        : "=r"(a) : "l"(p));
    return a;
}
__device__ __forceinline__ void cp16(void* dst_smem, const void* src) {
    uint32_t d = s2u(dst_smem);
    asm volatile("cp.async.ca.shared.global [%0], [%1], 16;" :: "r"(d), "l"(src) : "memory");
}
__device__ __forceinline__ void cp_commit() {
    asm volatile("cp.async.commit_group;" ::: "memory");
}
__device__ __forceinline__ void cp_wait0() {
    asm volatile("cp.async.wait_group 0;" ::: "memory");
}
__device__ __forceinline__ uint32_t swz(uint32_t o) { return o ^ ((o >> 3) & 0x70); }

__device__ __forceinline__ void ldm4(uint32_t* a, uint32_t addr) {
    asm volatile("ldmatrix.sync.aligned.m8n8.x4.shared.b16 {%0,%1,%2,%3}, [%4];"
        : "=r"(a[0]), "=r"(a[1]), "=r"(a[2]), "=r"(a[3]) : "r"(addr));
}
__device__ __forceinline__ void mma16816(float* d, const uint32_t* a, const uint32_t* b) {
    asm volatile(
        "mma.sync.aligned.m16n8k16.row.col.f32.bf16.bf16.f32 "
        "{%0,%1,%2,%3},{%4,%5,%6,%7},{%8,%9},{%0,%1,%2,%3};"
        : "+f"(d[0]), "+f"(d[1]), "+f"(d[2]), "+f"(d[3])
        : "r"(a[0]), "r"(a[1]), "r"(a[2]), "r"(a[3]), "r"(b[0]), "r"(b[1]));
}

// ============================================================
// prep body: split weights into bf16 hi/lo, transpose, swizzle
// ============================================================
__device__ void prep_body(const float* __restrict__ Wd2,
                          const float* __restrict__ Wg1,
                          const float* __restrict__ Wg2, int sub)
{
    if (threadIdx.x >= 128) return;
    int g  = sub >> 1;
    int kt = sub & 1;
    const float* W = (g == 0) ? Wd2 : ((g == 1) ? Wg1 : Wg2);
    int n = threadIdx.x;
    char* hi = (char*)(g_Wb + (size_t)((g * 2 + 0) * 2 + kt) * 8192);
    char* lo = (char*)(g_Wb + (size_t)((g * 2 + 1) * 2 + kt) * 8192);
    for (int kk = 0; kk < 64; kk++) {
        float v = W[(size_t)(kt * 64 + kk) * DM + n];
        __nv_bfloat16 h = __float2bfloat16(v);
        __nv_bfloat16 l = __float2bfloat16(v - __bfloat162float(h));
        uint32_t sw = swz(n * 128 + kk * 2);
        *(__nv_bfloat16*)(hi + sw) = h;
        *(__nv_bfloat16*)(lo + sw) = l;
    }
}

// ============================================================
// KNN body: 2 queries share each candidate load
// ============================================================
__device__ void knn_body(const float* __restrict__ xyz, float4* pts, int blk)
{
    int b    = blk >> 7;
    int tile = blk & 127;
    const float* base = xyz + (size_t)b * Nn * 3;
    for (int j = threadIdx.x; j < Nn; j += 256) {
        float x = base[j * 3 + 0], y = base[j * 3 + 1], z = base[j * 3 + 2];
        float sq = fmaf(z, z, fmaf(y, y, x * x));
        pts[j] = make_float4(x, y, z, 0.5f * sq);
    }
    __syncthreads();

    int warp = threadIdx.x >> 5, lane = threadIdx.x & 31;
    int q0 = tile * 32 + warp * 4;

    for (int qi = 0; qi < 4; qi += 2) {
        float4 qa = pts[q0 + qi];
        float4 qb = pts[q0 + qi + 1];

        float bdA[KK]; int biA[KK];
        float bdB[KK]; int biB[KK];
        #pragma unroll
        for (int i = 0; i < KK; i++) {
            bdA[i] = 3.4e38f; biA[i] = -1;
            bdB[i] = 3.4e38f; biB[i] = -1;
        }

        #pragma unroll 2
        for (int m = lane; m < Nn; m += 32) {
            float4 c = pts[m];
            float tA = c.w - fmaf(qa.z, c.z, fmaf(qa.y, c.y, qa.x * c.x));
            float tB = c.w - fmaf(qb.z, c.z, fmaf(qb.y, c.y, qb.x * c.x));
            if (tA < bdA[KK - 1]) {
                bdA[KK - 1] = tA; biA[KK - 1] = m;
                #pragma unroll
                for (int i = KK - 1; i > 0; i--) {
                    bool sw = bdA[i] < bdA[i - 1];
                    float td = bdA[i - 1]; int ti = biA[i - 1];
                    if (sw) {
                        bdA[i - 1] = bdA[i]; biA[i - 1] = biA[i];
                        bdA[i] = td;         biA[i] = ti;
                    }
                }
            }
            if (tB < bdB[KK - 1]) {
                bdB[KK - 1] = tB; biB[KK - 1] = m;
                #pragma unroll
                for (int i = KK - 1; i > 0; i--) {
                    bool sw = bdB[i] < bdB[i - 1];
                    float td = bdB[i - 1]; int ti = biB[i - 1];
                    if (sw) {
                        bdB[i - 1] = bdB[i]; biB[i - 1] = biB[i];
                        bdB[i] = td;         biB[i] = ti;
                    }
                }
            }
        }

        #pragma unroll 1
        for (int hq = 0; hq < 2; hq++) {
            float* bd = hq ? bdB : bdA;
            int*   bi = hq ? biB : biA;
            int keep = 0;
            #pragma unroll 1
            for (int r = 0; r < KK; r++) {
                float d = bd[0];
                float mn = d;
                #pragma unroll
                for (int off = 16; off; off >>= 1)
                    mn = fminf(mn, __shfl_xor_sync(0xffffffffu, mn, off));
                unsigned msk = __ballot_sync(0xffffffffu, d == mn);
                int owner = __ffs(msk) - 1;
                int widx  = __shfl_sync(0xffffffffu, bi[0], owner);
                if (lane == owner) {
                    #pragma unroll
                    for (int i = 0; i < KK - 1; i++) { bd[i] = bd[i + 1]; bi[i] = bi[i + 1]; }
                    bd[KK - 1] = 3.4e38f;
                }
                if (lane == r) keep = widx;
            }
            if (lane < KK)
                g_knn[((size_t)b * Nn + q0 + qi + hq) * KK + lane] = keep;
        }
    }
}

// ============================================================
// fqkv body: staged SIMT projections
// ============================================================
template<int NCH, int ASTR, int OSTR, bool RELU>
__device__ __forceinline__ void gemm_tile(
    const float* __restrict__ As, const float* __restrict__ W,
    const float* __restrict__ bias, float* __restrict__ Out,
    int tid, float* __restrict__ Wbuf)
{
    int r0 = (tid >> 4) * 4;
    int c0 = (tid & 15) * 8;
    float acc[4][8];
    #pragma unroll
    for (int i = 0; i < 4; i++)
        #pragma unroll
        for (int j = 0; j < 8; j++) acc[i][j] = 0.f;

    cp16(Wbuf + tid * 4, W + tid * 4);
    cp_commit();

    #pragma unroll 1
    for (int ch = 0; ch < NCH; ch++) {
        const float* cur = Wbuf + (ch & 1) * 1024;
        if (ch + 1 < NCH) {
            cp16(Wbuf + ((ch + 1) & 1) * 1024 + tid * 4,
                 W + (size_t)(ch + 1) * 1024 + tid * 4);
            cp_commit();
            asm volatile("cp.async.wait_group 1;" ::: "memory");
        } else {
            cp_wait0();
        }
        __syncthreads();

        #pragma unroll
        for (int k8 = 0; k8 < 8; k8++) {
            const float* wrow = cur + k8 * 128;
            float4 w0 = *reinterpret_cast<const float4*>(wrow + c0);
            float4 w1 = *reinterpret_cast<const float4*>(wrow + c0 + 4);
            float wv[8] = {w0.x, w0.y, w0.z, w0.w, w1.x, w1.y, w1.z, w1.w};
            int kk = ch * 8 + k8;
            float av[4];
            #pragma unroll
            for (int i = 0; i < 4; i++) av[i] = As[(r0 + i) * ASTR + kk];
            #pragma unroll
            for (int i = 0; i < 4; i++)
                #pragma unroll
                for (int j = 0; j < 8; j++)
                    acc[i][j] = fmaf(av[i], wv[j], acc[i][j]);
        }
        __syncthreads();
    }

    float bv[8];
    #pragma unroll
    for (int j = 0; j < 8; j++) bv[j] = bias ? bias[c0 + j] : 0.f;
    #pragma unroll
    for (int i = 0; i < 4; i++) {
        float v[8];
        #pragma unroll
        for (int j = 0; j < 8; j++) {
            v[j] = acc[i][j] + bv[j];
            if (RELU) v[j] = fmaxf(v[j], 0.f);
        }
        if (OSTR == 128) {
            float4* o = reinterpret_cast<float4*>(Out + (size_t)(r0 + i) * OSTR + c0);
            o[0] = make_float4(v[0], v[1], v[2], v[3]);
            o[1] = make_float4(v[4], v[5], v[6], v[7]);
        } else {
            #pragma unroll
            for (int j = 0; j < 8; j++)
                Out[(r0 + i) * OSTR + c0 + j] = v[j];
        }
    }
}

__device__ void fqkv_body(
    const float* __restrict__ features,
    const float* __restrict__ Wf1, const float* __restrict__ bf1,
    const float* __restrict__ Wq,  const float* __restrict__ Wk,
    const float* __restrict__ Wv, float* sm, int sub)
{
    float* s_x  = sm;
    float* s_f  = sm + 64 * 65;
    float* Wbuf = s_f + 64 * 129;

    int row0 = sub * 64;
    int tid  = threadIdx.x;

    for (int e = tid; e < 64 * DP; e += 256) {
        int r = e >> 6, c = e & 63;
        s_x[r * 65 + c] = features[(size_t)(row0 + r) * DP + c];
    }
    __syncthreads();

    gemm_tile<8, 65, 129, false>(s_x, Wf1, bf1, s_f, tid, Wbuf);
    gemm_tile<16, 129, 128, false>(s_f, Wq, nullptr, g_Q  + (size_t)row0 * DM, tid, Wbuf);
    gemm_tile<16, 129, 128, false>(s_f, Wk, nullptr, g_Kf + (size_t)row0 * DM, tid, Wbuf);
    gemm_tile<16, 129, 128, false>(s_f, Wv, nullptr, g_Vf + (size_t)row0 * DM, tid, Wbuf);
}

// ============================================================
// fat kernel: prep + knn + fqkv packed concurrently
// blocks [0,512): knn | [512,768): fqkv | [768,774): prep
// ============================================================
__global__ void __launch_bounds__(256) fat_kernel(
    const float* __restrict__ xyz, const float* __restrict__ features,
    const float* __restrict__ Wf1, const float* __restrict__ bf1,
    const float* __restrict__ Wq,  const float* __restrict__ Wk,
    const float* __restrict__ Wv,
    const float* __restrict__ Wd2, const float* __restrict__ Wg1,
    const float* __restrict__ Wg2)
{
    extern __shared__ char fsm[];
    int blk = blockIdx.x;
    if (blk < 512) {
        knn_body(xyz, (float4*)fsm, blk);
    } else if (blk < 768) {
        fqkv_body(features, Wf1, bf1, Wq, Wk, Wv, (float*)fsm, blk - 512);
    } else {
        prep_body(Wd2, Wg1, Wg2, blk - 768);
    }
}

// ============================================================
// A-tile split-bf16 stores (SW128 layout: [hi-k0][hi-k1][lo-k0][lo-k1])
// ============================================================
__device__ __forceinline__ void store8(char* a_t, int r, int c0, const float* v)
{
    int kt = c0 >> 6;
    uint32_t sw = swz(r * 128 + (c0 & 63) * 2);
    char* hib = a_t + kt * 16384;
    char* lob = a_t + 32768 + kt * 16384;
    uint32_t H[4], L[4];
    #pragma unroll
    for (int i = 0; i < 4; i++) {
        __nv_bfloat162 h = __floats2bfloat162_rn(v[2 * i], v[2 * i + 1]);
        float l0 = v[2 * i]     - __low2float(h);
        float l1 = v[2 * i + 1] - __high2float(h);
        __nv_bfloat162 l = __floats2bfloat162_rn(l0, l1);
        H[i] = *reinterpret_cast<uint32_t*>(&h);
        L[i] = *reinterpret_cast<uint32_t*>(&l);
    }
    *reinterpret_cast<uint4*>(hib + sw) = make_uint4(H[0], H[1], H[2], H[3]);
    *reinterpret_cast<uint4*>(lob + sw) = make_uint4(L[0], L[1], L[2], L[3]);
}
// packed pair store: (c,c+1), c even
__device__ __forceinline__ void stA2(char* a_t, int r, int c, float v0, float v1)
{
    int kt = c >> 6;
    uint32_t sw = swz(r * 128 + (c & 63) * 2);
    __nv_bfloat162 h = __floats2bfloat162_rn(v0, v1);
    float l0 = v0 - __low2float(h);
    float l1 = v1 - __high2float(h);
    __nv_bfloat162 l = __floats2bfloat162_rn(l0, l1);
    *reinterpret_cast<uint32_t*>(a_t + kt * 16384 + sw) = *reinterpret_cast<uint32_t*>(&h);
    *reinterpret_cast<uint32_t*>(a_t + 32768 + kt * 16384 + sw) = *reinterpret_cast<uint32_t*>(&l);
}

// ============================================================
// warp-level split-bf16 GEMM: warp computes rows [m0,m0+32) x
// cols [n0,n0+32) of D[128,128] = A @ W^T, 3 passes (4m x 4n grid).
// ============================================================
__device__ __forceinline__ void run_gemm_mma(
    uint32_t aB, uint32_t wB, int m0, int n0, int lane, float acc[2][4][4])
{
    #pragma unroll
    for (int mt = 0; mt < 2; mt++)
        #pragma unroll
        for (int ni = 0; ni < 4; ni++)
            #pragma unroll
            for (int e = 0; e < 4; e++) acc[mt][ni][e] = 0.f;

    int gsel   = lane >> 3;              // 0..3: (n-tile half, k-half)
    int b_nrow = (gsel >> 1) * 8 + (lane & 7);
    int b_koff = (gsel & 1) * 16;

    #pragma unroll
    for (int p = 0; p < 3; p++) {
        uint32_t aPB = aB + ((p == 2) ? 32768u : 0u);
        uint32_t wPB = wB + ((p == 1) ? 32768u : 0u);
        #pragma unroll
        for (int kt = 0; kt < 2; kt++) {
            uint32_t aT = aPB + kt * 16384;
            uint32_t wT = wPB + kt * 16384;
            #pragma unroll
            for (int ks = 0; ks < 4; ks++) {
                int kb = ks * 32 + ((lane >> 4) << 4);
                uint32_t a0[4], a1[4];
                ldm4(a0, aT + swz((m0      + (lane & 15)) * 128 + kb));
                ldm4(a1, aT + swz((m0 + 16 + (lane & 15)) * 128 + kb));
                #pragma unroll
                for (int nj = 0; nj < 2; nj++) {
                    int nrow = n0 + nj * 16 + b_nrow;
                    uint32_t b[4];
                    ldm4(b, wT + swz(nrow * 128 + ks * 32 + b_koff));
                    mma16816(acc[0][nj * 2],     a0, b);
                    mma16816(acc[0][nj * 2 + 1], a0, b + 2);
                    mma16816(acc[1][nj * 2],     a1, b);
                    mma16816(acc[1][nj * 2 + 1], a1, b + 2);
                }
            }
        }
    }
}

// ============================================================
// main kernel: 8 points (128 rows) / block, 512 threads,
// HMMA GEMMs (4m x 4n warps), E in registers, K/V/q staged.
// ============================================================
__global__ void __launch_bounds__(512, 1) main_kernel(
    const float* __restrict__ xyz,  const float* __restrict__ features,
    const float* __restrict__ Wd1,  const float* __restrict__ bd1,
    const float* __restrict__ bd2,
    const float* __restrict__ bg1,  const float* __restrict__ bg2,
    const float* __restrict__ Wo,   const float* __restrict__ bo,
    float* __restrict__ out)
{
    extern __shared__ char dsm[];
    uint32_t dbase = s2u(dsm);
    uint32_t pad = (1024u - (dbase & 1023u)) & 1023u;
    char*  a_t  = dsm + pad;                   // 4 x 16KB (hi0,hi1,lo0,lo1)
    char*  w_t  = a_t + 65536;                 // 4 x 16KB
    float* s_kv = (float*)(w_t + 65536);       // 128 x KV_STR floats (K, then V)

    __shared__ float s_wd1[3 * DM], s_bd1[DM], s_bd2[DM], s_bg1[DM], s_bg2[DM], s_bo[DP];
    __shared__ float s_res[8 * 129];
    __shared__ float s_q[8 * DM];
    __shared__ int   s_gi[128];

    const int tid  = threadIdx.x;
    const int wid  = tid >> 5;
    const int lane = tid & 31;
    const int blk  = blockIdx.x;
    const int m0   = (wid & 3) * 32;     // warp rows: 2 points
    const int n0   = (wid >> 2) * 32;    // warp col quarter

    // stage small weights/biases
    for (int i = tid; i < 3 * DM; i += 512) s_wd1[i] = Wd1[i];
    if (tid < DM) {
        s_bd1[tid] = bd1[tid]; s_bd2[tid] = bd2[tid];
        s_bg1[tid] = bg1[tid]; s_bg2[tid] = bg2[tid];
    }
    if (tid >= DM && tid < DM + DP) s_bo[tid - DM] = bo[tid - DM];

    // W tiles for GEMM 0
    {
        const char* src = (const char*)g_Wb;
        for (int i = tid; i < 4096; i += 512)
            cp16(w_t + i * 16, src + (size_t)i * 16);
        cp_commit();
    }

    // neighbor indices
    if (tid < 128) {
        int gp = blk * 8 + (tid >> 4);
        int bb = gp >> 12;
        int idx = g_knn[(size_t)gp * KK + (tid & 15)];
        s_gi[tid] = bb * Nn + idx;
    }
    __syncthreads();   // s_gi visible

    // stage K rows (gathered) + q rows via cp.async (overlaps stage1/GEMM0)
    {
        for (int i = tid; i < 4096; i += 512) {
            int row = i >> 5, seg = i & 31;
            cp16(s_kv + row * KV_STR + seg * 4,
                 g_Kf + (size_t)s_gi[row] * DM + seg * 4);
        }
        for (int i = tid; i < 256; i += 512) {
            int row = i >> 5, seg = i & 31;
            cp16(s_q + row * DM + seg * 4,
                 g_Q + (size_t)(blk * 8 + row) * DM + seg * 4);
        }
        cp_commit();
    }

    // stage 1: H = relu(rel @ Wd1 + bd1) -> A tiles (hi/lo)
    {
        int r  = tid & 127;
        int qq = tid >> 7;                  // 0..3 column quarter
        int gp = blk * 8 + (r >> 4);
        int gi = s_gi[r];
        float rx = xyz[(size_t)gp * 3 + 0] - xyz[(size_t)gi * 3 + 0];
        float ry = xyz[(size_t)gp * 3 + 1] - xyz[(size_t)gi * 3 + 1];
        float rz = xyz[(size_t)gp * 3 + 2] - xyz[(size_t)gi * 3 + 2];
        #pragma unroll
        for (int cg = 0; cg < 4; cg++) {
            int c0 = qq * 32 + cg * 8;
            float v[8];
            #pragma unroll
            for (int j = 0; j < 8; j++) {
                int c = c0 + j;
                float h = fmaf(rx, s_wd1[c], fmaf(ry, s_wd1[DM + c],
                           fmaf(rz, s_wd1[2 * DM + c], s_bd1[c])));
                v[j] = fmaxf(h, 0.f);
            }
            store8(a_t, r, c0, v);
        }
    }

    cp_wait0();        // W0 + K + q landed
    __syncthreads();   // visible to all; a_t ready

    uint32_t aB = s2u(a_t);
    uint32_t wB = s2u(w_t);
    float acc[2][4][4];
    float E[2][4][4];                     // pos_enc fragment (registers)

    // ---------------- GEMM 0: pos_enc ----------------
    run_gemm_mma(aB, wB, m0, n0, lane, acc);
    __syncthreads();                      // w_t free

    // prefetch W for GEMM 1
    {
        const char* src = (const char*)g_Wb + 65536;
        for (int i = tid; i < 4096; i += 512)
            cp16(w_t + i * 16, src + (size_t)i * 16);
        cp_commit();
    }

    // epilogue 0: E = D + bd2 (regs) ; A = q - k + E -> tiles (smem K/q)
    #pragma unroll
    for (int mt = 0; mt < 2; mt++) {
        int r0 = m0 + mt * 16 + (lane >> 2);
        int r1 = r0 + 8;
        int pt = (m0 >> 4) + mt;
        const float* qv = s_q  + pt * DM;
        const float* k0 = s_kv + r0 * KV_STR;
        const float* k1 = s_kv + r1 * KV_STR;
        #pragma unroll
        for (int ni = 0; ni < 4; ni++) {
            int c = n0 + ni * 8 + 2 * (lane & 3);
            float q0 = qv[c], q1 = qv[c + 1];
            E[mt][ni][0] = acc[mt][ni][0] + s_bd2[c];
            E[mt][ni][1] = acc[mt][ni][1] + s_bd2[c + 1];
            E[mt][ni][2] = acc[mt][ni][2] + s_bd2[c];
            E[mt][ni][3] = acc[mt][ni][3] + s_bd2[c + 1];
            stA2(a_t, r0, c, q0 - k0[c] + E[mt][ni][0], q1 - k0[c + 1] + E[mt][ni][1]);
            stA2(a_t, r1, c, q0 - k1[c] + E[mt][ni][2], q1 - k1[c + 1] + E[mt][ni][3]);
        }
    }
    cp_wait0();        // W1 landed
    __syncthreads();   // K fully consumed; a_t ready

    // stage V rows into s_kv (overlaps GEMM1/epilogue1/GEMM2)
    for (int i = tid; i < 4096; i += 512) {
        int row = i >> 5, seg = i & 31;
        cp16(s_kv + row * KV_STR + seg * 4,
             g_Vf + (size_t)s_gi[row] * DM + seg * 4);
    }
    cp_commit();

    // ---------------- GEMM 1: gamma layer 1 ----------------
    run_gemm_mma(aB, wB, m0, n0, lane, acc);
    __syncthreads();                      // w_t free

    // prefetch W for GEMM 2
    {
        const char* src = (const char*)g_Wb + 131072;
        for (int i = tid; i < 4096; i += 512)
            cp16(w_t + i * 16, src + (size_t)i * 16);
        cp_commit();
    }

    // epilogue 1: G = relu(D + bg1) -> tiles
    #pragma unroll
    for (int mt = 0; mt < 2; mt++) {
        int r0 = m0 + mt * 16 + (lane >> 2);
        int r1 = r0 + 8;
        #pragma unroll
        for (int ni = 0; ni < 4; ni++) {
            int c = n0 + ni * 8 + 2 * (lane & 3);
            stA2(a_t, r0, c, fmaxf(acc[mt][ni][0] + s_bg1[c],     0.f),
                             fmaxf(acc[mt][ni][1] + s_bg1[c + 1], 0.f));
            stA2(a_t, r1, c, fmaxf(acc[mt][ni][2] + s_bg1[c],     0.f),
                             fmaxf(acc[mt][ni][3] + s_bg1[c + 1], 0.f));
        }
    }
    cp_wait0();        // W2 + V landed
    __syncthreads();

    // ---------------- GEMM 2: gamma layer 2 ----------------
    run_gemm_mma(aB, wB, m0, n0, lane, acc);

    // epilogue 2: softmax over the 16 k-rows of each warp point
    // (no barrier needed: reads only own regs + V smem staged above)
    {
        const float inv_s = 0.08838834764831845f;   // 1/sqrt(128)
        #pragma unroll
        for (int mt = 0; mt < 2; mt++) {
            int r0 = m0 + mt * 16 + (lane >> 2);
            int r1 = r0 + 8;
            int pt = (m0 >> 4) + mt;
            const float* v0r = s_kv + r0 * KV_STR;
            const float* v1r = s_kv + r1 * KV_STR;
            #pragma unroll
            for (int ni = 0; ni < 4; ni++) {
                int c = n0 + ni * 8 + 2 * (lane & 3);
                float l0 = acc[mt][ni][0] + s_bg2[c];       // (r0, c)
                float l1 = acc[mt][ni][1] + s_bg2[c + 1];   // (r0, c+1)
                float l2 = acc[mt][ni][2] + s_bg2[c];       // (r1, c)
                float l3 = acc[mt][ni][3] + s_bg2[c + 1];   // (r1, c+1)
                float mA = fmaxf(l0, l2), mB = fmaxf(l1, l3);
                #pragma unroll
                for (int off = 4; off <= 16; off <<= 1) {
                    mA = fmaxf(mA, __shfl_xor_sync(0xffffffffu, mA, off));
                    mB = fmaxf(mB, __shfl_xor_sync(0xffffffffu, mB, off));
                }
                float e0 = __expf((l0 - mA) * inv_s);
                float e2 = __expf((l2 - mA) * inv_s);
                float e1 = __expf((l1 - mB) * inv_s);
                float e3 = __expf((l3 - mB) * inv_s);
                float vE0 = v0r[c]     + E[mt][ni][0];
                float vE1 = v0r[c + 1] + E[mt][ni][1];
                float vE2 = v1r[c]     + E[mt][ni][2];
                float vE3 = v1r[c + 1] + E[mt][ni][3];
                float sA = e0 + e2,                sB = e1 + e3;
                float nA = fmaf(e0, vE0, e2 * vE2), nB = fmaf(e1, vE1, e3 * vE3);
                #pragma unroll
                for (int off = 4; off <= 16; off <<= 1) {
                    sA += __shfl_xor_sync(0xffffffffu, sA, off);
                    sB += __shfl_xor_sync(0xffffffffu, sB, off);
                    nA += __shfl_xor_sync(0xffffffffu, nA, off);
                    nB += __shfl_xor_sync(0xffffffffu, nB, off);
                }
                if ((lane >> 2) == 0) {
                    s_res[pt * 129 + c]     = nA / sA;
                    s_res[pt * 129 + c + 1] = nB / sB;
                }
            }
        }
    }
    __syncthreads();

    // output: out = res @ Wo + bo + features   [8,64] (one elem/thread)
    {
        int pp = tid >> 6, j = tid & 63;
        float acc2 = s_bo[j];
        #pragma unroll 4
        for (int c = 0; c < DM; c++)
            acc2 = fmaf(s_res[pp * 129 + c], Wo[(size_t)c * DP + j], acc2);
        int go = blk * 8 + pp;
        out[(size_t)go * DP + j] = acc2 + features[(size_t)go * DP + j];
    }
}

// ============================================================
extern "C" void kernel_launch(void* const* d_in, const int* in_sizes, int n_in,
                              void* d_out, int out_size)
{
    (void)in_sizes; (void)n_in; (void)out_size;
    const float* xyz      = (const float*)d_in[0];
    const float* features = (const float*)d_in[1];
    const float* Wd1 = (const float*)d_in[2];
    const float* bd1 = (const float*)d_in[3];
    const float* Wd2 = (const float*)d_in[4];
    const float* bd2 = (const float*)d_in[5];
    const float* Wf1 = (const float*)d_in[6];
    const float* bf1 = (const float*)d_in[7];
    const float* Wq  = (const float*)d_in[8];
    const float* Wk  = (const float*)d_in[9];
    const float* Wv  = (const float*)d_in[10];
    const float* Wg1 = (const float*)d_in[11];
    const float* bg1 = (const float*)d_in[12];
    const float* Wg2 = (const float*)d_in[13];
    const float* bg2 = (const float*)d_in[14];
    const float* Wo  = (const float*)d_in[15];
    const float* bo  = (const float*)d_in[16];
    float* out = (float*)d_out;

    size_t sh_fat = (size_t)Nn * sizeof(float4);    // 64KB (covers knn + fqkv)
    cudaFuncSetAttribute(fat_kernel,
                         cudaFuncAttributeMaxDynamicSharedMemorySize, (int)sh_fat);
    fat_kernel<<<774, 256, sh_fat>>>(xyz, features, Wf1, bf1, Wq, Wk, Wv,
                                     Wd2, Wg1, Wg2);

    size_t sh_main = 1024 + 65536 + 65536 + (size_t)128 * KV_STR * sizeof(float);
    cudaFuncSetAttribute(main_kernel,
                         cudaFuncAttributeMaxDynamicSharedMemorySize, (int)sh_main);
    main_kernel<<<BN / 8, 512, sh_main>>>(xyz, features,
                                          Wd1, bd1, bd2, bg1, bg2,
                                          Wo, bo, out);
}

// round 12
// speedup vs baseline: 1.2441x; 1.2441x over previous
#include <cuda_runtime.h>
#include <cuda_bf16.h>
#include <cstdint>

#define Bb 4
#define Nn 4096
#define KK 16
#define DP 64
#define DM 128
#define BN (Bb*Nn)

// ---- scratch (device globals: allocation-free) ----
__device__ int   g_knn[BN*KK];
__device__ float g_Q [BN*DM];
__device__ float g_Kf[BN*DM];
__device__ float g_Vf[BN*DM];
// pre-split/transposed/swizzled weight tile images:
// [gemm(3)][half hi/lo][ktile(2)] x (128 rows x 64 bf16) = 12 x 16KB
__device__ __nv_bfloat16 g_Wb[3*2*2*128*64];

#define KV_STR 136   // floats per staged K/V row (bank spreading, 16B aligned)

// ============================================================
// helpers
// ============================================================
__device__ __forceinline__ uint32_t s2u(const void* p) {
    uint32_t a;
    asm("{ .reg .u64 t; cvta.to.shared.u64 t, %1; cvt.u32.u64 %0, t; }"
        : "=r"(a) : "l"(p));
    return a;
}
__device__ __forceinline__ void cp16(void* dst_smem, const void* src) {
    uint32_t d = s2u(dst_smem);
    asm volatile("cp.async.ca.shared.global [%0], [%1], 16;" :: "r"(d), "l"(src) : "memory");
}
__device__ __forceinline__ void cp_commit() {
    asm volatile("cp.async.commit_group;" ::: "memory");
}
__device__ __forceinline__ void cp_wait0() {
    asm volatile("cp.async.wait_group 0;" ::: "memory");
}
__device__ __forceinline__ uint32_t swz(uint32_t o) { return o ^ ((o >> 3) & 0x70); }

__device__ __forceinline__ void ldm4(uint32_t* a, uint32_t addr) {
    asm volatile("ldmatrix.sync.aligned.m8n8.x4.shared.b16 {%0,%1,%2,%3}, [%4];"
        : "=r"(a[0]), "=r"(a[1]), "=r"(a[2]), "=r"(a[3]) : "r"(addr));
}
__device__ __forceinline__ void mma16816(float* d, const uint32_t* a, const uint32_t* b) {
    asm volatile(
        "mma.sync.aligned.m16n8k16.row.col.f32.bf16.bf16.f32 "
        "{%0,%1,%2,%3},{%4,%5,%6,%7},{%8,%9},{%0,%1,%2,%3};"
        : "+f"(d[0]), "+f"(d[1]), "+f"(d[2]), "+f"(d[3])
        : "r"(a[0]), "r"(a[1]), "r"(a[2]), "r"(a[3]), "r"(b[0]), "r"(b[1]));
}

// ============================================================
// prep: split weights into bf16 hi/lo, transpose to [n][k] and
// bake the SW128 swizzle (B operand images for mma.row.col).
// ============================================================
__global__ void __launch_bounds__(128) prep_w(
    const float* __restrict__ Wd2, const float* __restrict__ Wg1,
    const float* __restrict__ Wg2)
{
    int g  = blockIdx.x >> 1;
    int kt = blockIdx.x & 1;
    const float* W = (g == 0) ? Wd2 : ((g == 1) ? Wg1 : Wg2);
    int n = threadIdx.x;
    char* hi = (char*)(g_Wb + (size_t)((g * 2 + 0) * 2 + kt) * 8192);
    char* lo = (char*)(g_Wb + (size_t)((g * 2 + 1) * 2 + kt) * 8192);
    for (int kk = 0; kk < 64; kk++) {
        float v = W[(size_t)(kt * 64 + kk) * DM + n];
        __nv_bfloat16 h = __float2bfloat16(v);
        __nv_bfloat16 l = __float2bfloat16(v - __bfloat162float(h));
        uint32_t sw = swz(n * 128 + kk * 2);
        *(__nv_bfloat16*)(hi + sw) = h;
        *(__nv_bfloat16*)(lo + sw) = l;
    }
}

// ============================================================
// KNN: float4 (x,y,z,0.5*|p|^2) smem; select on t = 0.5*csq - dot
// (monotonic transform of d2 for fixed query -> same top-16 set/order)
// ============================================================
__global__ void __launch_bounds__(256) knn_kernel(const float* __restrict__ xyz)
{
    extern __shared__ float4 pts[];
    int b = blockIdx.x;
    const float* base = xyz + (size_t)b * Nn * 3;
    for (int j = threadIdx.x; j < Nn; j += blockDim.x) {
        float x = base[j * 3 + 0], y = base[j * 3 + 1], z = base[j * 3 + 2];
        float sq = fmaf(z, z, fmaf(y, y, x * x));
        pts[j] = make_float4(x, y, z, 0.5f * sq);
    }
    __syncthreads();

    int warp = threadIdx.x >> 5, lane = threadIdx.x & 31;
    int q0 = blockIdx.y * 32 + warp * 4;

    for (int qi = 0; qi < 4; qi++) {
        int q = q0 + qi;
        float4 qp = pts[q];
        float qx = qp.x, qy = qp.y, qz = qp.z;

        float bd[KK]; int bi[KK];
        #pragma unroll
        for (int i = 0; i < KK; i++) { bd[i] = 3.4e38f; bi[i] = -1; }

        #pragma unroll 4
        for (int m = lane; m < Nn; m += 32) {
            float4 c = pts[m];
            float s = fmaf(qy, c.y, qx * c.x);
            float t = c.w - fmaf(qz, c.z, s);      // 0.5*d2 - 0.5*qsq
            if (t < bd[KK - 1]) {
                bd[KK - 1] = t; bi[KK - 1] = m;
                #pragma unroll
                for (int i = KK - 1; i > 0; i--) {
                    bool sw = bd[i] < bd[i - 1];
                    float td = bd[i - 1]; int ti = bi[i - 1];
                    if (sw) {
                        bd[i - 1] = bd[i]; bi[i - 1] = bi[i];
                        bd[i] = td;        bi[i] = ti;
                    }
                }
            }
        }

        int keep = 0;
        #pragma unroll 1
        for (int r = 0; r < KK; r++) {
            float d = bd[0];
            float mn = d;
            #pragma unroll
            for (int off = 16; off; off >>= 1)
                mn = fminf(mn, __shfl_xor_sync(0xffffffffu, mn, off));
            unsigned msk = __ballot_sync(0xffffffffu, d == mn);
            int owner = __ffs(msk) - 1;
            int widx  = __shfl_sync(0xffffffffu, bi[0], owner);
            if (lane == owner) {
                #pragma unroll
                for (int i = 0; i < KK - 1; i++) { bd[i] = bd[i + 1]; bi[i] = bi[i + 1]; }
                bd[KK - 1] = 3.4e38f;
            }
            if (lane == r) keep = widx;
        }
        if (lane < KK) g_knn[((size_t)b * Nn + q) * KK + lane] = keep;
    }
}

// ============================================================
// fqkv: staged SIMT projections
// ============================================================
template<int NCH, int ASTR, int OSTR, bool RELU>
__device__ __forceinline__ void gemm_tile(
    const float* __restrict__ As, const float* __restrict__ W,
    const float* __restrict__ bias, float* __restrict__ Out,
    int tid, float* __restrict__ Wbuf)
{
    int r0 = (tid >> 4) * 4;
    int c0 = (tid & 15) * 8;
    float acc[4][8];
    #pragma unroll
    for (int i = 0; i < 4; i++)
        #pragma unroll
        for (int j = 0; j < 8; j++) acc[i][j] = 0.f;

    cp16(Wbuf + tid * 4, W + tid * 4);
    cp_commit();

    #pragma unroll 1
    for (int ch = 0; ch < NCH; ch++) {
        const float* cur = Wbuf + (ch & 1) * 1024;
        if (ch + 1 < NCH) {
            cp16(Wbuf + ((ch + 1) & 1) * 1024 + tid * 4,
                 W + (size_t)(ch + 1) * 1024 + tid * 4);
            cp_commit();
            asm volatile("cp.async.wait_group 1;" ::: "memory");
        } else {
            cp_wait0();
        }
        __syncthreads();

        #pragma unroll
        for (int k8 = 0; k8 < 8; k8++) {
            const float* wrow = cur + k8 * 128;
            float4 w0 = *reinterpret_cast<const float4*>(wrow + c0);
            float4 w1 = *reinterpret_cast<const float4*>(wrow + c0 + 4);
            float wv[8] = {w0.x, w0.y, w0.z, w0.w, w1.x, w1.y, w1.z, w1.w};
            int kk = ch * 8 + k8;
            float av[4];
            #pragma unroll
            for (int i = 0; i < 4; i++) av[i] = As[(r0 + i) * ASTR + kk];
            #pragma unroll
            for (int i = 0; i < 4; i++)
                #pragma unroll
                for (int j = 0; j < 8; j++)
                    acc[i][j] = fmaf(av[i], wv[j], acc[i][j]);
        }
        __syncthreads();
    }

    float bv[8];
    #pragma unroll
    for (int j = 0; j < 8; j++) bv[j] = bias ? bias[c0 + j] : 0.f;
    #pragma unroll
    for (int i = 0; i < 4; i++) {
        float v[8];
        #pragma unroll
        for (int j = 0; j < 8; j++) {
            v[j] = acc[i][j] + bv[j];
            if (RELU) v[j] = fmaxf(v[j], 0.f);
        }
        if (OSTR == 128) {
            float4* o = reinterpret_cast<float4*>(Out + (size_t)(r0 + i) * OSTR + c0);
            o[0] = make_float4(v[0], v[1], v[2], v[3]);
            o[1] = make_float4(v[4], v[5], v[6], v[7]);
        } else {
            #pragma unroll
            for (int j = 0; j < 8; j++)
                Out[(r0 + i) * OSTR + c0 + j] = v[j];
        }
    }
}

__global__ void __launch_bounds__(256) fqkv_kernel(
    const float* __restrict__ features,
    const float* __restrict__ Wf1, const float* __restrict__ bf1,
    const float* __restrict__ Wq,  const float* __restrict__ Wk,
    const float* __restrict__ Wv)
{
    extern __shared__ float sm[];
    float* s_x  = sm;
    float* s_f  = sm + 64 * 65;
    float* Wbuf = s_f + 64 * 129;

    int row0 = blockIdx.x * 64;
    int tid  = threadIdx.x;

    for (int e = tid; e < 64 * DP; e += 256) {
        int r = e >> 6, c = e & 63;
        s_x[r * 65 + c] = features[(size_t)(row0 + r) * DP + c];
    }
    __syncthreads();

    gemm_tile<8, 65, 129, false>(s_x, Wf1, bf1, s_f, tid, Wbuf);
    gemm_tile<16, 129, 128, false>(s_f, Wq, nullptr, g_Q  + (size_t)row0 * DM, tid, Wbuf);
    gemm_tile<16, 129, 128, false>(s_f, Wk, nullptr, g_Kf + (size_t)row0 * DM, tid, Wbuf);
    gemm_tile<16, 129, 128, false>(s_f, Wv, nullptr, g_Vf + (size_t)row0 * DM, tid, Wbuf);
}

// ============================================================
// A-tile split-bf16 stores (SW128 layout: [hi-k0][hi-k1][lo-k0][lo-k1])
// ============================================================
__device__ __forceinline__ void store8(char* a_t, int r, int c0, const float* v)
{
    int kt = c0 >> 6;
    uint32_t sw = swz(r * 128 + (c0 & 63) * 2);
    char* hib = a_t + kt * 16384;
    char* lob = a_t + 32768 + kt * 16384;
    uint32_t H[4], L[4];
    #pragma unroll
    for (int i = 0; i < 4; i++) {
        __nv_bfloat162 h = __floats2bfloat162_rn(v[2 * i], v[2 * i + 1]);
        float l0 = v[2 * i]     - __low2float(h);
        float l1 = v[2 * i + 1] - __high2float(h);
        __nv_bfloat162 l = __floats2bfloat162_rn(l0, l1);
        H[i] = *reinterpret_cast<uint32_t*>(&h);
        L[i] = *reinterpret_cast<uint32_t*>(&l);
    }
    *reinterpret_cast<uint4*>(hib + sw) = make_uint4(H[0], H[1], H[2], H[3]);
    *reinterpret_cast<uint4*>(lob + sw) = make_uint4(L[0], L[1], L[2], L[3]);
}
// packed pair store: (c,c+1), c even
__device__ __forceinline__ void stA2(char* a_t, int r, int c, float v0, float v1)
{
    int kt = c >> 6;
    uint32_t sw = swz(r * 128 + (c & 63) * 2);
    __nv_bfloat162 h = __floats2bfloat162_rn(v0, v1);
    float l0 = v0 - __low2float(h);
    float l1 = v1 - __high2float(h);
    __nv_bfloat162 l = __floats2bfloat162_rn(l0, l1);
    *reinterpret_cast<uint32_t*>(a_t + kt * 16384 + sw) = *reinterpret_cast<uint32_t*>(&h);
    *reinterpret_cast<uint32_t*>(a_t + 32768 + kt * 16384 + sw) = *reinterpret_cast<uint32_t*>(&l);
}

// ============================================================
// warp-level split-bf16 GEMM: warp computes rows [m0,m0+32) x
// cols [n0,n0+32) of D[128,128] = A @ W^T, 3 passes (4m x 4n grid).
// ============================================================
__device__ __forceinline__ void run_gemm_mma(
    uint32_t aB, uint32_t wB, int m0, int n0, int lane, float acc[2][4][4])
{
    #pragma unroll
    for (int mt = 0; mt < 2; mt++)
        #pragma unroll
        for (int ni = 0; ni < 4; ni++)
            #pragma unroll
            for (int e = 0; e < 4; e++) acc[mt][ni][e] = 0.f;

    int gsel   = lane >> 3;              // 0..3: (n-tile half, k-half)
    int b_nrow = (gsel >> 1) * 8 + (lane & 7);
    int b_koff = (gsel & 1) * 16;

    #pragma unroll
    for (int p = 0; p < 3; p++) {
        uint32_t aPB = aB + ((p == 2) ? 32768u : 0u);
        uint32_t wPB = wB + ((p == 1) ? 32768u : 0u);
        #pragma unroll
        for (int kt = 0; kt < 2; kt++) {
            uint32_t aT = aPB + kt * 16384;
            uint32_t wT = wPB + kt * 16384;
            #pragma unroll
            for (int ks = 0; ks < 4; ks++) {
                int kb = ks * 32 + ((lane >> 4) << 4);
                uint32_t a0[4], a1[4];
                ldm4(a0, aT + swz((m0      + (lane & 15)) * 128 + kb));
                ldm4(a1, aT + swz((m0 + 16 + (lane & 15)) * 128 + kb));
                #pragma unroll
                for (int nj = 0; nj < 2; nj++) {
                    int nrow = n0 + nj * 16 + b_nrow;
                    uint32_t b[4];
                    ldm4(b, wT + swz(nrow * 128 + ks * 32 + b_koff));
                    mma16816(acc[0][nj * 2],     a0, b);
                    mma16816(acc[0][nj * 2 + 1], a0, b + 2);
                    mma16816(acc[1][nj * 2],     a1, b);
                    mma16816(acc[1][nj * 2 + 1], a1, b + 2);
                }
            }
        }
    }
}

// ============================================================
// main kernel: 8 points (128 rows) / block, 512 threads,
// HMMA GEMMs (4m x 4n warps), E in registers, K/V/q staged,
// Wo staged into a_t during epilogue 2.
// ============================================================
__global__ void __launch_bounds__(512, 1) main_kernel(
    const float* __restrict__ xyz,  const float* __restrict__ features,
    const float* __restrict__ Wd1,  const float* __restrict__ bd1,
    const float* __restrict__ bd2,
    const float* __restrict__ bg1,  const float* __restrict__ bg2,
    const float* __restrict__ Wo,   const float* __restrict__ bo,
    float* __restrict__ out)
{
    extern __shared__ char dsm[];
    uint32_t dbase = s2u(dsm);
    uint32_t pad = (1024u - (dbase & 1023u)) & 1023u;
    char*  a_t  = dsm + pad;                   // 4 x 16KB (hi0,hi1,lo0,lo1)
    char*  w_t  = a_t + 65536;                 // 4 x 16KB
    float* s_kv = (float*)(w_t + 65536);       // 128 x KV_STR floats (K, then V)
    float* s_wo = (float*)a_t;                 // Wo staged here after GEMM2

    __shared__ float s_wd1[3 * DM], s_bd1[DM], s_bd2[DM], s_bg1[DM], s_bg2[DM], s_bo[DP];
    __shared__ float s_res[8 * 129];
    __shared__ float s_q[8 * DM];
    __shared__ int   s_gi[128];

    const int tid  = threadIdx.x;
    const int wid  = tid >> 5;
    const int lane = tid & 31;
    const int blk  = blockIdx.x;
    const int m0   = (wid & 3) * 32;     // warp rows: 2 points
    const int n0   = (wid >> 2) * 32;    // warp col quarter

    // stage small weights/biases
    for (int i = tid; i < 3 * DM; i += 512) s_wd1[i] = Wd1[i];
    if (tid < DM) {
        s_bd1[tid] = bd1[tid]; s_bd2[tid] = bd2[tid];
        s_bg1[tid] = bg1[tid]; s_bg2[tid] = bg2[tid];
    }
    if (tid >= DM && tid < DM + DP) s_bo[tid - DM] = bo[tid - DM];

    // W tiles for GEMM 0
    {
        const char* src = (const char*)g_Wb;
        for (int i = tid; i < 4096; i += 512)
            cp16(w_t + i * 16, src + (size_t)i * 16);
        cp_commit();
    }

    // neighbor indices
    if (tid < 128) {
        int gp = blk * 8 + (tid >> 4);
        int bb = gp >> 12;
        int idx = g_knn[(size_t)gp * KK + (tid & 15)];
        s_gi[tid] = bb * Nn + idx;
    }
    __syncthreads();   // s_gi visible

    // stage K rows (gathered) + q rows via cp.async (overlaps stage1/GEMM0)
    {
        for (int i = tid; i < 4096; i += 512) {
            int row = i >> 5, seg = i & 31;
            cp16(s_kv + row * KV_STR + seg * 4,
                 g_Kf + (size_t)s_gi[row] * DM + seg * 4);
        }
        for (int i = tid; i < 256; i += 512) {
            int row = i >> 5, seg = i & 31;
            cp16(s_q + row * DM + seg * 4,
                 g_Q + (size_t)(blk * 8 + row) * DM + seg * 4);
        }
        cp_commit();
    }

    // stage 1: H = relu(rel @ Wd1 + bd1) -> A tiles (hi/lo)
    {
        int r  = tid & 127;
        int qq = tid >> 7;                  // 0..3 column quarter
        int gp = blk * 8 + (r >> 4);
        int gi = s_gi[r];
        float rx = xyz[(size_t)gp * 3 + 0] - xyz[(size_t)gi * 3 + 0];
        float ry = xyz[(size_t)gp * 3 + 1] - xyz[(size_t)gi * 3 + 1];
        float rz = xyz[(size_t)gp * 3 + 2] - xyz[(size_t)gi * 3 + 2];
        #pragma unroll
        for (int cg = 0; cg < 4; cg++) {
            int c0 = qq * 32 + cg * 8;
            float v[8];
            #pragma unroll
            for (int j = 0; j < 8; j++) {
                int c = c0 + j;
                float h = fmaf(rx, s_wd1[c], fmaf(ry, s_wd1[DM + c],
                           fmaf(rz, s_wd1[2 * DM + c], s_bd1[c])));
                v[j] = fmaxf(h, 0.f);
            }
            store8(a_t, r, c0, v);
        }
    }

    cp_wait0();        // W0 + K + q landed
    __syncthreads();   // visible to all; a_t ready

    uint32_t aB = s2u(a_t);
    uint32_t wB = s2u(w_t);
    float acc[2][4][4];
    float E[2][4][4];                     // pos_enc fragment (registers)

    // ---------------- GEMM 0: pos_enc ----------------
    run_gemm_mma(aB, wB, m0, n0, lane, acc);
    __syncthreads();                      // w_t free

    // prefetch W for GEMM 1
    {
        const char* src = (const char*)g_Wb + 65536;
        for (int i = tid; i < 4096; i += 512)
            cp16(w_t + i * 16, src + (size_t)i * 16);
        cp_commit();
    }

    // epilogue 0: E = D + bd2 (regs) ; A = q - k + E -> tiles (smem K/q)
    #pragma unroll
    for (int mt = 0; mt < 2; mt++) {
        int r0 = m0 + mt * 16 + (lane >> 2);
        int r1 = r0 + 8;
        int pt = (m0 >> 4) + mt;
        const float* qv = s_q  + pt * DM;
        const float* k0 = s_kv + r0 * KV_STR;
        const float* k1 = s_kv + r1 * KV_STR;
        #pragma unroll
        for (int ni = 0; ni < 4; ni++) {
            int c = n0 + ni * 8 + 2 * (lane & 3);
            float q0 = qv[c], q1 = qv[c + 1];
            E[mt][ni][0] = acc[mt][ni][0] + s_bd2[c];
            E[mt][ni][1] = acc[mt][ni][1] + s_bd2[c + 1];
            E[mt][ni][2] = acc[mt][ni][2] + s_bd2[c];
            E[mt][ni][3] = acc[mt][ni][3] + s_bd2[c + 1];
            stA2(a_t, r0, c, q0 - k0[c] + E[mt][ni][0], q1 - k0[c + 1] + E[mt][ni][1]);
            stA2(a_t, r1, c, q0 - k1[c] + E[mt][ni][2], q1 - k1[c + 1] + E[mt][ni][3]);
        }
    }
    cp_wait0();        // W1 landed
    __syncthreads();   // K fully consumed; a_t ready

    // stage V rows into s_kv (overlaps GEMM1/epilogue1/GEMM2)
    for (int i = tid; i < 4096; i += 512) {
        int row = i >> 5, seg = i & 31;
        cp16(s_kv + row * KV_STR + seg * 4,
             g_Vf + (size_t)s_gi[row] * DM + seg * 4);
    }
    cp_commit();

    // ---------------- GEMM 1: gamma layer 1 ----------------
    run_gemm_mma(aB, wB, m0, n0, lane, acc);
    __syncthreads();                      // w_t free

    // prefetch W for GEMM 2
    {
        const char* src = (const char*)g_Wb + 131072;
        for (int i = tid; i < 4096; i += 512)
            cp16(w_t + i * 16, src + (size_t)i * 16);
        cp_commit();
    }

    // epilogue 1: G = relu(D + bg1) -> tiles
    #pragma unroll
    for (int mt = 0; mt < 2; mt++) {
        int r0 = m0 + mt * 16 + (lane >> 2);
        int r1 = r0 + 8;
        #pragma unroll
        for (int ni = 0; ni < 4; ni++) {
            int c = n0 + ni * 8 + 2 * (lane & 3);
            stA2(a_t, r0, c, fmaxf(acc[mt][ni][0] + s_bg1[c],     0.f),
                             fmaxf(acc[mt][ni][1] + s_bg1[c + 1], 0.f));
            stA2(a_t, r1, c, fmaxf(acc[mt][ni][2] + s_bg1[c],     0.f),
                             fmaxf(acc[mt][ni][3] + s_bg1[c + 1], 0.f));
        }
    }
    cp_wait0();        // W2 + V landed
    __syncthreads();

    // ---------------- GEMM 2: gamma layer 2 ----------------
    run_gemm_mma(aB, wB, m0, n0, lane, acc);
    __syncthreads();                      // a_t fully consumed by all warps

    // stage Wo into a_t (overlaps softmax epilogue)
    for (int i = tid; i < 2048; i += 512)
        cp16((char*)s_wo + i * 16, (const char*)Wo + (size_t)i * 16);
    cp_commit();

    // epilogue 2: softmax over the 16 k-rows of each warp point
    {
        const float inv_s = 0.08838834764831845f;   // 1/sqrt(128)
        #pragma unroll
        for (int mt = 0; mt < 2; mt++) {
            int r0 = m0 + mt * 16 + (lane >> 2);
            int r1 = r0 + 8;
            int pt = (m0 >> 4) + mt;
            const float* v0r = s_kv + r0 * KV_STR;
            const float* v1r = s_kv + r1 * KV_STR;
            #pragma unroll
            for (int ni = 0; ni < 4; ni++) {
                int c = n0 + ni * 8 + 2 * (lane & 3);
                float l0 = acc[mt][ni][0] + s_bg2[c];       // (r0, c)
                float l1 = acc[mt][ni][1] + s_bg2[c + 1];   // (r0, c+1)
                float l2 = acc[mt][ni][2] + s_bg2[c];       // (r1, c)
                float l3 = acc[mt][ni][3] + s_bg2[c + 1];   // (r1, c+1)
                float mA = fmaxf(l0, l2), mB = fmaxf(l1, l3);
                #pragma unroll
                for (int off = 4; off <= 16; off <<= 1) {
                    mA = fmaxf(mA, __shfl_xor_sync(0xffffffffu, mA, off));
                    mB = fmaxf(mB, __shfl_xor_sync(0xffffffffu, mB, off));
                }
                float e0 = __expf((l0 - mA) * inv_s);
                float e2 = __expf((l2 - mA) * inv_s);
                float e1 = __expf((l1 - mB) * inv_s);
                float e3 = __expf((l3 - mB) * inv_s);
                float vE0 = v0r[c]     + E[mt][ni][0];
                float vE1 = v0r[c + 1] + E[mt][ni][1];
                float vE2 = v1r[c]     + E[mt][ni][2];
                float vE3 = v1r[c + 1] + E[mt][ni][3];
                float sA = e0 + e2,                sB = e1 + e3;
                float nA = fmaf(e0, vE0, e2 * vE2), nB = fmaf(e1, vE1, e3 * vE3);
                #pragma unroll
                for (int off = 4; off <= 16; off <<= 1) {
                    sA += __shfl_xor_sync(0xffffffffu, sA, off);
                    sB += __shfl_xor_sync(0xffffffffu, sB, off);
                    nA += __shfl_xor_sync(0xffffffffu, nA, off);
                    nB += __shfl_xor_sync(0xffffffffu, nB, off);
                }
                if ((lane >> 2) == 0) {
                    s_res[pt * 129 + c]     = nA / sA;
                    s_res[pt * 129 + c + 1] = nB / sB;
                }
            }
        }
    }
    cp_wait0();        // Wo landed
    __syncthreads();   // s_res + s_wo visible

    // output: out = res @ Wo + bo + features   [8,64] (one elem/thread)
    {
        int pp = tid >> 6, j = tid & 63;
        float acc2 = s_bo[j];
        #pragma unroll 4
        for (int c = 0; c < DM; c++)
            acc2 = fmaf(s_res[pp * 129 + c], s_wo[c * DP + j], acc2);
        int go = blk * 8 + pp;
        out[(size_t)go * DP + j] = acc2 + features[(size_t)go * DP + j];
    }
}

// ============================================================
extern "C" void kernel_launch(void* const* d_in, const int* in_sizes, int n_in,
                              void* d_out, int out_size)
{
    (void)in_sizes; (void)n_in; (void)out_size;
    const float* xyz      = (const float*)d_in[0];
    const float* features = (const float*)d_in[1];
    const float* Wd1 = (const float*)d_in[2];
    const float* bd1 = (const float*)d_in[3];
    const float* Wd2 = (const float*)d_in[4];
    const float* bd2 = (const float*)d_in[5];
    const float* Wf1 = (const float*)d_in[6];
    const float* bf1 = (const float*)d_in[7];
    const float* Wq  = (const float*)d_in[8];
    const float* Wk  = (const float*)d_in[9];
    const float* Wv  = (const float*)d_in[10];
    const float* Wg1 = (const float*)d_in[11];
    const float* bg1 = (const float*)d_in[12];
    const float* Wg2 = (const float*)d_in[13];
    const float* bg2 = (const float*)d_in[14];
    const float* Wo  = (const float*)d_in[15];
    const float* bo  = (const float*)d_in[16];
    float* out = (float*)d_out;

    prep_w<<<6, 128>>>(Wd2, Wg1, Wg2);

    size_t sh_knn = (size_t)Nn * sizeof(float4);
    cudaFuncSetAttribute(knn_kernel,
                         cudaFuncAttributeMaxDynamicSharedMemorySize, (int)sh_knn);
    knn_kernel<<<dim3(Bb, Nn / 32), 256, sh_knn>>>(xyz);

    size_t sh_fqkv = (64 * 65 + 64 * 129 + 2048) * sizeof(float);
    cudaFuncSetAttribute(fqkv_kernel,
                         cudaFuncAttributeMaxDynamicSharedMemorySize, (int)sh_fqkv);
    fqkv_kernel<<<BN / 64, 256, sh_fqkv>>>(features, Wf1, bf1, Wq, Wk, Wv);

    size_t sh_main = 1024 + 65536 + 65536 + (size_t)128 * KV_STR * sizeof(float);
    cudaFuncSetAttribute(main_kernel,
                         cudaFuncAttributeMaxDynamicSharedMemorySize, (int)sh_main);
    main_kernel<<<BN / 8, 512, sh_main>>>(xyz, features,
                                          Wd1, bd1, bd2, bg1, bg2,
                                          Wo, bo, out);
}

// round 13
// speedup vs baseline: 1.4614x; 1.1746x over previous
#include <cuda_runtime.h>
#include <cuda_bf16.h>
#include <cstdint>

#define Bb 4
#define Nn 4096
#define KK 16
#define DP 64
#define DM 128
#define BN (Bb*Nn)

// ---- scratch (device globals: allocation-free) ----
__device__ int   g_knn[BN*KK];
__device__ float g_Q [BN*DM];
__device__ float g_Kf[BN*DM];
__device__ float g_Vf[BN*DM];
// pre-split/transposed/swizzled weight tile images:
// [gemm(3)][half hi/lo][ktile(2)] x (128 rows x 64 bf16) = 12 x 16KB
__device__ __nv_bfloat16 g_Wb[3*2*2*128*64];

#define KV_STR 136   // floats per staged K/V row (bank spreading, 16B aligned)

// ============================================================
// helpers
// ============================================================
__device__ __forceinline__ uint32_t s2u(const void* p) {
    uint32_t a;
    asm("{ .reg .u64 t; cvta.to.shared.u64 t, %1; cvt.u32.u64 %0, t; }"
        : "=r"(a) : "l"(p));
    return a;
}
__device__ __forceinline__ void cp16(void* dst_smem, const void* src) {
    uint32_t d = s2u(dst_smem);
    asm volatile("cp.async.ca.shared.global [%0], [%1], 16;" :: "r"(d), "l"(src) : "memory");
}
__device__ __forceinline__ void cp_commit() {
    asm volatile("cp.async.commit_group;" ::: "memory");
}
__device__ __forceinline__ void cp_wait0() {
    asm volatile("cp.async.wait_group 0;" ::: "memory");
}
__device__ __forceinline__ uint32_t swz(uint32_t o) { return o ^ ((o >> 3) & 0x70); }

__device__ __forceinline__ void ldm4(uint32_t* a, uint32_t addr) {
    asm volatile("ldmatrix.sync.aligned.m8n8.x4.shared.b16 {%0,%1,%2,%3}, [%4];"
        : "=r"(a[0]), "=r"(a[1]), "=r"(a[2]), "=r"(a[3]) : "r"(addr));
}
__device__ __forceinline__ void mma16816(float* d, const uint32_t* a, const uint32_t* b) {
    asm volatile(
        "mma.sync.aligned.m16n8k16.row.col.f32.bf16.bf16.f32 "
        "{%0,%1,%2,%3},{%4,%5,%6,%7},{%8,%9},{%0,%1,%2,%3};"
        : "+f"(d[0]), "+f"(d[1]), "+f"(d[2]), "+f"(d[3])
        : "r"(a[0]), "r"(a[1]), "r"(a[2]), "r"(a[3]), "r"(b[0]), "r"(b[1]));
}

// packed fp32x2 helpers (Blackwell)
__device__ __forceinline__ void lds2u64(unsigned long long& a, unsigned long long& b,
                                        uint32_t addr) {
    asm volatile("ld.shared.v2.u64 {%0,%1}, [%2];" : "=l"(a), "=l"(b) : "r"(addr));
}
__device__ __forceinline__ unsigned long long packf2(float lo, float hi) {
    unsigned long long r;
    asm("mov.b64 %0, {%1,%2};" : "=l"(r) : "f"(lo), "f"(hi));
    return r;
}
__device__ __forceinline__ void unpackf2(float& lo, float& hi, unsigned long long v) {
    asm("mov.b64 {%0,%1}, %2;" : "=f"(lo), "=f"(hi) : "l"(v));
}
__device__ __forceinline__ unsigned long long mulx2(unsigned long long a,
                                                    unsigned long long b) {
    unsigned long long r;
    asm("mul.rn.f32x2 %0, %1, %2;" : "=l"(r) : "l"(a), "l"(b));
    return r;
}
__device__ __forceinline__ unsigned long long fmax2(unsigned long long a,
                                                    unsigned long long b,
                                                    unsigned long long c) {
    unsigned long long r;
    asm("fma.rn.f32x2 %0, %1, %2, %3;" : "=l"(r) : "l"(a), "l"(b), "l"(c));
    return r;
}

// ============================================================
// prep: split weights into bf16 hi/lo, transpose to [n][k] and
// bake the SW128 swizzle (B operand images for mma.row.col).
// ============================================================
__global__ void __launch_bounds__(128) prep_w(
    const float* __restrict__ Wd2, const float* __restrict__ Wg1,
    const float* __restrict__ Wg2)
{
    int g  = blockIdx.x >> 1;
    int kt = blockIdx.x & 1;
    const float* W = (g == 0) ? Wd2 : ((g == 1) ? Wg1 : Wg2);
    int n = threadIdx.x;
    char* hi = (char*)(g_Wb + (size_t)((g * 2 + 0) * 2 + kt) * 8192);
    char* lo = (char*)(g_Wb + (size_t)((g * 2 + 1) * 2 + kt) * 8192);
    for (int kk = 0; kk < 64; kk++) {
        float v = W[(size_t)(kt * 64 + kk) * DM + n];
        __nv_bfloat16 h = __float2bfloat16(v);
        __nv_bfloat16 l = __float2bfloat16(v - __bfloat162float(h));
        uint32_t sw = swz(n * 128 + kk * 2);
        *(__nv_bfloat16*)(hi + sw) = h;
        *(__nv_bfloat16*)(lo + sw) = l;
    }
}

// ============================================================
// KNN: pairwise-packed smem [x0,x1,y0,y1 | z0,z1,w0,w1] per pair;
// 2 candidates per iteration via fp32x2 packed math. The per-
// candidate rounding sequence (mul.rn, fma.rn, fma.rn, rn(w-d))
// is identical to the scalar version -> same selection.
// ============================================================
__global__ void __launch_bounds__(256) knn_kernel(const float* __restrict__ xyz)
{
    extern __shared__ float pf[];     // Nn/2 pairs * 8 floats = 64KB
    int b = blockIdx.x;
    const float* base = xyz + (size_t)b * Nn * 3;
    for (int j = threadIdx.x; j < Nn; j += blockDim.x) {
        float x = base[j * 3 + 0], y = base[j * 3 + 1], z = base[j * 3 + 2];
        float sq = fmaf(z, z, fmaf(y, y, x * x));
        int p = j >> 1, h = j & 1;
        pf[p * 8 + 0 + h] = x;
        pf[p * 8 + 2 + h] = y;
        pf[p * 8 + 4 + h] = z;
        pf[p * 8 + 6 + h] = 0.5f * sq;
    }
    __syncthreads();

    uint32_t ptsBase = s2u(pf);
    int warp = threadIdx.x >> 5, lane = threadIdx.x & 31;
    int q0 = blockIdx.y * 32 + warp * 4;
    const unsigned long long negOne = packf2(-1.0f, -1.0f);

    for (int qi = 0; qi < 4; qi++) {
        int q = q0 + qi;
        const float* qp = pf + (q >> 1) * 8 + (q & 1);
        float qx = qp[0], qy = qp[2], qz = qp[4];
        unsigned long long qxx = packf2(qx, qx);
        unsigned long long qyy = packf2(qy, qy);
        unsigned long long qzz = packf2(qz, qz);

        float bd[KK]; int bi[KK];
        #pragma unroll
        for (int i = 0; i < KK; i++) { bd[i] = 3.4e38f; bi[i] = -1; }

        #pragma unroll 2
        for (int p = lane; p < Nn / 2; p += 32) {
            unsigned long long x01, y01, z01, w01;
            uint32_t ad = ptsBase + p * 32;
            lds2u64(x01, y01, ad);
            lds2u64(z01, w01, ad + 16);
            unsigned long long d = mulx2(x01, qxx);
            d = fmax2(y01, qyy, d);
            d = fmax2(z01, qzz, d);
            unsigned long long t2 = fmax2(d, negOne, w01);   // w - dot
            float tA, tB;
            unpackf2(tA, tB, t2);
            if (tA < bd[KK - 1]) {
                bd[KK - 1] = tA; bi[KK - 1] = 2 * p;
                #pragma unroll
                for (int i = KK - 1; i > 0; i--) {
                    bool sw = bd[i] < bd[i - 1];
                    float td = bd[i - 1]; int ti = bi[i - 1];
                    if (sw) {
                        bd[i - 1] = bd[i]; bi[i - 1] = bi[i];
                        bd[i] = td;        bi[i] = ti;
                    }
                }
            }
            if (tB < bd[KK - 1]) {
                bd[KK - 1] = tB; bi[KK - 1] = 2 * p + 1;
                #pragma unroll
                for (int i = KK - 1; i > 0; i--) {
                    bool sw = bd[i] < bd[i - 1];
                    float td = bd[i - 1]; int ti = bi[i - 1];
                    if (sw) {
                        bd[i - 1] = bd[i]; bi[i - 1] = bi[i];
                        bd[i] = td;        bi[i] = ti;
                    }
                }
            }
        }

        int keep = 0;
        #pragma unroll 1
        for (int r = 0; r < KK; r++) {
            float d = bd[0];
            float mn = d;
            #pragma unroll
            for (int off = 16; off; off >>= 1)
                mn = fminf(mn, __shfl_xor_sync(0xffffffffu, mn, off));
            unsigned msk = __ballot_sync(0xffffffffu, d == mn);
            int owner = __ffs(msk) - 1;
            int widx  = __shfl_sync(0xffffffffu, bi[0], owner);
            if (lane == owner) {
                #pragma unroll
                for (int i = 0; i < KK - 1; i++) { bd[i] = bd[i + 1]; bi[i] = bi[i + 1]; }
                bd[KK - 1] = 3.4e38f;
            }
            if (lane == r) keep = widx;
        }
        if (lane < KK) g_knn[((size_t)b * Nn + q) * KK + lane] = keep;
    }
}

// ============================================================
// fqkv: staged SIMT projections
// ============================================================
template<int NCH, int ASTR, int OSTR, bool RELU>
__device__ __forceinline__ void gemm_tile(
    const float* __restrict__ As, const float* __restrict__ W,
    const float* __restrict__ bias, float* __restrict__ Out,
    int tid, float* __restrict__ Wbuf)
{
    int r0 = (tid >> 4) * 4;
    int c0 = (tid & 15) * 8;
    float acc[4][8];
    #pragma unroll
    for (int i = 0; i < 4; i++)
        #pragma unroll
        for (int j = 0; j < 8; j++) acc[i][j] = 0.f;

    cp16(Wbuf + tid * 4, W + tid * 4);
    cp_commit();

    #pragma unroll 1
    for (int ch = 0; ch < NCH; ch++) {
        const float* cur = Wbuf + (ch & 1) * 1024;
        if (ch + 1 < NCH) {
            cp16(Wbuf + ((ch + 1) & 1) * 1024 + tid * 4,
                 W + (size_t)(ch + 1) * 1024 + tid * 4);
            cp_commit();
            asm volatile("cp.async.wait_group 1;" ::: "memory");
        } else {
            cp_wait0();
        }
        __syncthreads();

        #pragma unroll
        for (int k8 = 0; k8 < 8; k8++) {
            const float* wrow = cur + k8 * 128;
            float4 w0 = *reinterpret_cast<const float4*>(wrow + c0);
            float4 w1 = *reinterpret_cast<const float4*>(wrow + c0 + 4);
            float wv[8] = {w0.x, w0.y, w0.z, w0.w, w1.x, w1.y, w1.z, w1.w};
            int kk = ch * 8 + k8;
            float av[4];
            #pragma unroll
            for (int i = 0; i < 4; i++) av[i] = As[(r0 + i) * ASTR + kk];
            #pragma unroll
            for (int i = 0; i < 4; i++)
                #pragma unroll
                for (int j = 0; j < 8; j++)
                    acc[i][j] = fmaf(av[i], wv[j], acc[i][j]);
        }
        __syncthreads();
    }

    float bv[8];
    #pragma unroll
    for (int j = 0; j < 8; j++) bv[j] = bias ? bias[c0 + j] : 0.f;
    #pragma unroll
    for (int i = 0; i < 4; i++) {
        float v[8];
        #pragma unroll
        for (int j = 0; j < 8; j++) {
            v[j] = acc[i][j] + bv[j];
            if (RELU) v[j] = fmaxf(v[j], 0.f);
        }
        if (OSTR == 128) {
            float4* o = reinterpret_cast<float4*>(Out + (size_t)(r0 + i) * OSTR + c0);
            o[0] = make_float4(v[0], v[1], v[2], v[3]);
            o[1] = make_float4(v[4], v[5], v[6], v[7]);
        } else {
            #pragma unroll
            for (int j = 0; j < 8; j++)
                Out[(r0 + i) * OSTR + c0 + j] = v[j];
        }
    }
}

__global__ void __launch_bounds__(256) fqkv_kernel(
    const float* __restrict__ features,
    const float* __restrict__ Wf1, const float* __restrict__ bf1,
    const float* __restrict__ Wq,  const float* __restrict__ Wk,
    const float* __restrict__ Wv)
{
    extern __shared__ float sm[];
    float* s_x  = sm;
    float* s_f  = sm + 64 * 65;
    float* Wbuf = s_f + 64 * 129;

    int row0 = blockIdx.x * 64;
    int tid  = threadIdx.x;

    for (int e = tid; e < 64 * DP; e += 256) {
        int r = e >> 6, c = e & 63;
        s_x[r * 65 + c] = features[(size_t)(row0 + r) * DP + c];
    }
    __syncthreads();

    gemm_tile<8, 65, 129, false>(s_x, Wf1, bf1, s_f, tid, Wbuf);
    gemm_tile<16, 129, 128, false>(s_f, Wq, nullptr, g_Q  + (size_t)row0 * DM, tid, Wbuf);
    gemm_tile<16, 129, 128, false>(s_f, Wk, nullptr, g_Kf + (size_t)row0 * DM, tid, Wbuf);
    gemm_tile<16, 129, 128, false>(s_f, Wv, nullptr, g_Vf + (size_t)row0 * DM, tid, Wbuf);
}

// ============================================================
// A-tile split-bf16 stores (SW128 layout: [hi-k0][hi-k1][lo-k0][lo-k1])
// ============================================================
__device__ __forceinline__ void store8(char* a_t, int r, int c0, const float* v)
{
    int kt = c0 >> 6;
    uint32_t sw = swz(r * 128 + (c0 & 63) * 2);
    char* hib = a_t + kt * 16384;
    char* lob = a_t + 32768 + kt * 16384;
    uint32_t H[4], L[4];
    #pragma unroll
    for (int i = 0; i < 4; i++) {
        __nv_bfloat162 h = __floats2bfloat162_rn(v[2 * i], v[2 * i + 1]);
        float l0 = v[2 * i]     - __low2float(h);
        float l1 = v[2 * i + 1] - __high2float(h);
        __nv_bfloat162 l = __floats2bfloat162_rn(l0, l1);
        H[i] = *reinterpret_cast<uint32_t*>(&h);
        L[i] = *reinterpret_cast<uint32_t*>(&l);
    }
    *reinterpret_cast<uint4*>(hib + sw) = make_uint4(H[0], H[1], H[2], H[3]);
    *reinterpret_cast<uint4*>(lob + sw) = make_uint4(L[0], L[1], L[2], L[3]);
}
// packed pair store: (c,c+1), c even
__device__ __forceinline__ void stA2(char* a_t, int r, int c, float v0, float v1)
{
    int kt = c >> 6;
    uint32_t sw = swz(r * 128 + (c & 63) * 2);
    __nv_bfloat162 h = __floats2bfloat162_rn(v0, v1);
    float l0 = v0 - __low2float(h);
    float l1 = v1 - __high2float(h);
    __nv_bfloat162 l = __floats2bfloat162_rn(l0, l1);
    *reinterpret_cast<uint32_t*>(a_t + kt * 16384 + sw) = *reinterpret_cast<uint32_t*>(&h);
    *reinterpret_cast<uint32_t*>(a_t + 32768 + kt * 16384 + sw) = *reinterpret_cast<uint32_t*>(&l);
}

// ============================================================
// warp-level split-bf16 GEMM: warp computes rows [m0,m0+32) x
// cols [n0,n0+32) of D[128,128] = A @ W^T.
// SINGLE k-loop: fragments loaded once per (kt,ks), all 3
// correction passes issued from registers (hi*hi + hi*lo + lo*hi).
// ============================================================
__device__ __forceinline__ void run_gemm_mma(
    uint32_t aB, uint32_t wB, int m0, int n0, int lane, float acc[2][4][4])
{
    #pragma unroll
    for (int mt = 0; mt < 2; mt++)
        #pragma unroll
        for (int ni = 0; ni < 4; ni++)
            #pragma unroll
            for (int e = 0; e < 4; e++) acc[mt][ni][e] = 0.f;

    int gsel   = lane >> 3;              // 0..3: (n-tile half, k-half)
    int b_nrow = (gsel >> 1) * 8 + (lane & 7);
    int b_koff = (gsel & 1) * 16;

    #pragma unroll
    for (int kt = 0; kt < 2; kt++) {
        uint32_t aHT = aB + kt * 16384,  aLT = aB + 32768 + kt * 16384;
        uint32_t wHT = wB + kt * 16384,  wLT = wB + 32768 + kt * 16384;
        #pragma unroll
        for (int ks = 0; ks < 4; ks++) {
            int kb = ks * 32 + ((lane >> 4) << 4);
            uint32_t ah0[4], ah1[4], al0[4], al1[4];
            ldm4(ah0, aHT + swz((m0      + (lane & 15)) * 128 + kb));
            ldm4(ah1, aHT + swz((m0 + 16 + (lane & 15)) * 128 + kb));
            ldm4(al0, aLT + swz((m0      + (lane & 15)) * 128 + kb));
            ldm4(al1, aLT + swz((m0 + 16 + (lane & 15)) * 128 + kb));
            #pragma unroll
            for (int nj = 0; nj < 2; nj++) {
                int nrow = n0 + nj * 16 + b_nrow;
                uint32_t bh[4], bl[4];
                ldm4(bh, wHT + swz(nrow * 128 + ks * 32 + b_koff));
                ldm4(bl, wLT + swz(nrow * 128 + ks * 32 + b_koff));
                // hi * hi
                mma16816(acc[0][nj * 2],     ah0, bh);
                mma16816(acc[0][nj * 2 + 1], ah0, bh + 2);
                mma16816(acc[1][nj * 2],     ah1, bh);
                mma16816(acc[1][nj * 2 + 1], ah1, bh + 2);
                // hi * lo
                mma16816(acc[0][nj * 2],     ah0, bl);
                mma16816(acc[0][nj * 2 + 1], ah0, bl + 2);
                mma16816(acc[1][nj * 2],     ah1, bl);
                mma16816(acc[1][nj * 2 + 1], ah1, bl + 2);
                // lo * hi
                mma16816(acc[0][nj * 2],     al0, bh);
                mma16816(acc[0][nj * 2 + 1], al0, bh + 2);
                mma16816(acc[1][nj * 2],     al1, bh);
                mma16816(acc[1][nj * 2 + 1], al1, bh + 2);
            }
        }
    }
}

// ============================================================
// main kernel: 8 points (128 rows) / block, 512 threads,
// HMMA GEMMs (4m x 4n warps), E in registers, K/V/q staged,
// Wo staged into a_t during epilogue 2.
// ============================================================
__global__ void __launch_bounds__(512, 1) main_kernel(
    const float* __restrict__ xyz,  const float* __restrict__ features,
    const float* __restrict__ Wd1,  const float* __restrict__ bd1,
    const float* __restrict__ bd2,
    const float* __restrict__ bg1,  const float* __restrict__ bg2,
    const float* __restrict__ Wo,   const float* __restrict__ bo,
    float* __restrict__ out)
{
    extern __shared__ char dsm[];
    uint32_t dbase = s2u(dsm);
    uint32_t pad = (1024u - (dbase & 1023u)) & 1023u;
    char*  a_t  = dsm + pad;                   // 4 x 16KB (hi0,hi1,lo0,lo1)
    char*  w_t  = a_t + 65536;                 // 4 x 16KB
    float* s_kv = (float*)(w_t + 65536);       // 128 x KV_STR floats (K, then V)
    float* s_wo = (float*)a_t;                 // Wo staged here after GEMM2

    __shared__ float s_wd1[3 * DM], s_bd1[DM], s_bd2[DM], s_bg1[DM], s_bg2[DM], s_bo[DP];
    __shared__ float s_res[8 * 129];
    __shared__ float s_q[8 * DM];
    __shared__ int   s_gi[128];

    const int tid  = threadIdx.x;
    const int wid  = tid >> 5;
    const int lane = tid & 31;
    const int blk  = blockIdx.x;
    const int m0   = (wid & 3) * 32;     // warp rows: 2 points
    const int n0   = (wid >> 2) * 32;    // warp col quarter

    // stage small weights/biases
    for (int i = tid; i < 3 * DM; i += 512) s_wd1[i] = Wd1[i];
    if (tid < DM) {
        s_bd1[tid] = bd1[tid]; s_bd2[tid] = bd2[tid];
        s_bg1[tid] = bg1[tid]; s_bg2[tid] = bg2[tid];
    }
    if (tid >= DM && tid < DM + DP) s_bo[tid - DM] = bo[tid - DM];

    // W tiles for GEMM 0
    {
        const char* src = (const char*)g_Wb;
        for (int i = tid; i < 4096; i += 512)
            cp16(w_t + i * 16, src + (size_t)i * 16);
        cp_commit();
    }

    // neighbor indices
    if (tid < 128) {
        int gp = blk * 8 + (tid >> 4);
        int bb = gp >> 12;
        int idx = g_knn[(size_t)gp * KK + (tid & 15)];
        s_gi[tid] = bb * Nn + idx;
    }
    __syncthreads();   // s_gi visible

    // stage K rows (gathered) + q rows via cp.async (overlaps stage1/GEMM0)
    {
        for (int i = tid; i < 4096; i += 512) {
            int row = i >> 5, seg = i & 31;
            cp16(s_kv + row * KV_STR + seg * 4,
                 g_Kf + (size_t)s_gi[row] * DM + seg * 4);
        }
        for (int i = tid; i < 256; i += 512) {
            int row = i >> 5, seg = i & 31;
            cp16(s_q + row * DM + seg * 4,
                 g_Q + (size_t)(blk * 8 + row) * DM + seg * 4);
        }
        cp_commit();
    }

    // stage 1: H = relu(rel @ Wd1 + bd1) -> A tiles (hi/lo)
    {
        int r  = tid & 127;
        int qq = tid >> 7;                  // 0..3 column quarter
        int gp = blk * 8 + (r >> 4);
        int gi = s_gi[r];
        float rx = xyz[(size_t)gp * 3 + 0] - xyz[(size_t)gi * 3 + 0];
        float ry = xyz[(size_t)gp * 3 + 1] - xyz[(size_t)gi * 3 + 1];
        float rz = xyz[(size_t)gp * 3 + 2] - xyz[(size_t)gi * 3 + 2];
        #pragma unroll
        for (int cg = 0; cg < 4; cg++) {
            int c0 = qq * 32 + cg * 8;
            float v[8];
            #pragma unroll
            for (int j = 0; j < 8; j++) {
                int c = c0 + j;
                float h = fmaf(rx, s_wd1[c], fmaf(ry, s_wd1[DM + c],
                           fmaf(rz, s_wd1[2 * DM + c], s_bd1[c])));
                v[j] = fmaxf(h, 0.f);
            }
            store8(a_t, r, c0, v);
        }
    }

    cp_wait0();        // W0 + K + q landed
    __syncthreads();   // visible to all; a_t ready

    uint32_t aB = s2u(a_t);
    uint32_t wB = s2u(w_t);
    float acc[2][4][4];
    float E[2][4][4];                     // pos_enc fragment (registers)

    // ---------------- GEMM 0: pos_enc ----------------
    run_gemm_mma(aB, wB, m0, n0, lane, acc);
    __syncthreads();                      // w_t free

    // prefetch W for GEMM 1
    {
        const char* src = (const char*)g_Wb + 65536;
        for (int i = tid; i < 4096; i += 512)
            cp16(w_t + i * 16, src + (size_t)i * 16);
        cp_commit();
    }

    // epilogue 0: E = D + bd2 (regs) ; A = q - k + E -> tiles (smem K/q)
    #pragma unroll
    for (int mt = 0; mt < 2; mt++) {
        int r0 = m0 + mt * 16 + (lane >> 2);
        int r1 = r0 + 8;
        int pt = (m0 >> 4) + mt;
        const float* qv = s_q  + pt * DM;
        const float* k0 = s_kv + r0 * KV_STR;
        const float* k1 = s_kv + r1 * KV_STR;
        #pragma unroll
        for (int ni = 0; ni < 4; ni++) {
            int c = n0 + ni * 8 + 2 * (lane & 3);
            float q0 = qv[c], q1 = qv[c + 1];
            E[mt][ni][0] = acc[mt][ni][0] + s_bd2[c];
            E[mt][ni][1] = acc[mt][ni][1] + s_bd2[c + 1];
            E[mt][ni][2] = acc[mt][ni][2] + s_bd2[c];
            E[mt][ni][3] = acc[mt][ni][3] + s_bd2[c + 1];
            stA2(a_t, r0, c, q0 - k0[c] + E[mt][ni][0], q1 - k0[c + 1] + E[mt][ni][1]);
            stA2(a_t, r1, c, q0 - k1[c] + E[mt][ni][2], q1 - k1[c + 1] + E[mt][ni][3]);
        }
    }
    cp_wait0();        // W1 landed
    __syncthreads();   // K fully consumed; a_t ready

    // stage V rows into s_kv (overlaps GEMM1/epilogue1/GEMM2)
    for (int i = tid; i < 4096; i += 512) {
        int row = i >> 5, seg = i & 31;
        cp16(s_kv + row * KV_STR + seg * 4,
             g_Vf + (size_t)s_gi[row] * DM + seg * 4);
    }
    cp_commit();

    // ---------------- GEMM 1: gamma layer 1 ----------------
    run_gemm_mma(aB, wB, m0, n0, lane, acc);
    __syncthreads();                      // w_t free

    // prefetch W for GEMM 2
    {
        const char* src = (const char*)g_Wb + 131072;
        for (int i = tid; i < 4096; i += 512)
            cp16(w_t + i * 16, src + (size_t)i * 16);
        cp_commit();
    }

    // epilogue 1: G = relu(D + bg1) -> tiles
    #pragma unroll
    for (int mt = 0; mt < 2; mt++) {
        int r0 = m0 + mt * 16 + (lane >> 2);
        int r1 = r0 + 8;
        #pragma unroll
        for (int ni = 0; ni < 4; ni++) {
            int c = n0 + ni * 8 + 2 * (lane & 3);
            stA2(a_t, r0, c, fmaxf(acc[mt][ni][0] + s_bg1[c],     0.f),
                             fmaxf(acc[mt][ni][1] + s_bg1[c + 1], 0.f));
            stA2(a_t, r1, c, fmaxf(acc[mt][ni][2] + s_bg1[c],     0.f),
                             fmaxf(acc[mt][ni][3] + s_bg1[c + 1], 0.f));
        }
    }
    cp_wait0();        // W2 + V landed
    __syncthreads();

    // ---------------- GEMM 2: gamma layer 2 ----------------
    run_gemm_mma(aB, wB, m0, n0, lane, acc);
    __syncthreads();                      // a_t fully consumed by all warps

    // stage Wo into a_t (overlaps softmax epilogue)
    for (int i = tid; i < 2048; i += 512)
        cp16((char*)s_wo + i * 16, (const char*)Wo + (size_t)i * 16);
    cp_commit();

    // epilogue 2: softmax over the 16 k-rows of each warp point
    {
        const float inv_s = 0.08838834764831845f;   // 1/sqrt(128)
        #pragma unroll
        for (int mt = 0; mt < 2; mt++) {
            int r0 = m0 + mt * 16 + (lane >> 2);
            int r1 = r0 + 8;
            int pt = (m0 >> 4) + mt;
            const float* v0r = s_kv + r0 * KV_STR;
            const float* v1r = s_kv + r1 * KV_STR;
            #pragma unroll
            for (int ni = 0; ni < 4; ni++) {
                int c = n0 + ni * 8 + 2 * (lane & 3);
                float l0 = acc[mt][ni][0] + s_bg2[c];       // (r0, c)
                float l1 = acc[mt][ni][1] + s_bg2[c + 1];   // (r0, c+1)
                float l2 = acc[mt][ni][2] + s_bg2[c];       // (r1, c)
                float l3 = acc[mt][ni][3] + s_bg2[c + 1];   // (r1, c+1)
                float mA = fmaxf(l0, l2), mB = fmaxf(l1, l3);
                #pragma unroll
                for (int off = 4; off <= 16; off <<= 1) {
                    mA = fmaxf(mA, __shfl_xor_sync(0xffffffffu, mA, off));
                    mB = fmaxf(mB, __shfl_xor_sync(0xffffffffu, mB, off));
                }
                float e0 = __expf((l0 - mA) * inv_s);
                float e2 = __expf((l2 - mA) * inv_s);
                float e1 = __expf((l1 - mB) * inv_s);
                float e3 = __expf((l3 - mB) * inv_s);
                float vE0 = v0r[c]     + E[mt][ni][0];
                float vE1 = v0r[c + 1] + E[mt][ni][1];
                float vE2 = v1r[c]     + E[mt][ni][2];
                float vE3 = v1r[c + 1] + E[mt][ni][3];
                float sA = e0 + e2,                sB = e1 + e3;
                float nA = fmaf(e0, vE0, e2 * vE2), nB = fmaf(e1, vE1, e3 * vE3);
                #pragma unroll
                for (int off = 4; off <= 16; off <<= 1) {
                    sA += __shfl_xor_sync(0xffffffffu, sA, off);
                    sB += __shfl_xor_sync(0xffffffffu, sB, off);
                    nA += __shfl_xor_sync(0xffffffffu, nA, off);
                    nB += __shfl_xor_sync(0xffffffffu, nB, off);
                }
                if ((lane >> 2) == 0) {
                    s_res[pt * 129 + c]     = nA / sA;
                    s_res[pt * 129 + c + 1] = nB / sB;
                }
            }
        }
    }
    cp_wait0();        // Wo landed
    __syncthreads();   // s_res + s_wo visible

    // output: out = res @ Wo + bo + features   [8,64] (one elem/thread)
    {
        int pp = tid >> 6, j = tid & 63;
        float acc2 = s_bo[j];
        #pragma unroll 4
        for (int c = 0; c < DM; c++)
            acc2 = fmaf(s_res[pp * 129 + c], s_wo[c * DP + j], acc2);
        int go = blk * 8 + pp;
        out[(size_t)go * DP + j] = acc2 + features[(size_t)go * DP + j];
    }
}

// ============================================================
extern "C" void kernel_launch(void* const* d_in, const int* in_sizes, int n_in,
                              void* d_out, int out_size)
{
    (void)in_sizes; (void)n_in; (void)out_size;
    const float* xyz      = (const float*)d_in[0];
    const float* features = (const float*)d_in[1];
    const float* Wd1 = (const float*)d_in[2];
    const float* bd1 = (const float*)d_in[3];
    const float* Wd2 = (const float*)d_in[4];
    const float* bd2 = (const float*)d_in[5];
    const float* Wf1 = (const float*)d_in[6];
    const float* bf1 = (const float*)d_in[7];
    const float* Wq  = (const float*)d_in[8];
    const float* Wk  = (const float*)d_in[9];
    const float* Wv  = (const float*)d_in[10];
    const float* Wg1 = (const float*)d_in[11];
    const float* bg1 = (const float*)d_in[12];
    const float* Wg2 = (const float*)d_in[13];
    const float* bg2 = (const float*)d_in[14];
    const float* Wo  = (const float*)d_in[15];
    const float* bo  = (const float*)d_in[16];
    float* out = (float*)d_out;

    prep_w<<<6, 128>>>(Wd2, Wg1, Wg2);

    size_t sh_knn = (size_t)Nn * 4 * sizeof(float);   // 64KB packed pairs
    cudaFuncSetAttribute(knn_kernel,
                         cudaFuncAttributeMaxDynamicSharedMemorySize, (int)sh_knn);
    knn_kernel<<<dim3(Bb, Nn / 32), 256, sh_knn>>>(xyz);

    size_t sh_fqkv = (64 * 65 + 64 * 129 + 2048) * sizeof(float);
    cudaFuncSetAttribute(fqkv_kernel,
                         cudaFuncAttributeMaxDynamicSharedMemorySize, (int)sh_fqkv);
    fqkv_kernel<<<BN / 64, 256, sh_fqkv>>>(features, Wf1, bf1, Wq, Wk, Wv);

    size_t sh_main = 1024 + 65536 + 65536 + (size_t)128 * KV_STR * sizeof(float);
    cudaFuncSetAttribute(main_kernel,
                         cudaFuncAttributeMaxDynamicSharedMemorySize, (int)sh_main);
    main_kernel<<<BN / 8, 512, sh_main>>>(xyz, features,
                                          Wd1, bd1, bd2, bg1, bg2,
                                          Wo, bo, out);
}